// round 16
// baseline (speedup 1.0000x reference)
#include <cuda_runtime.h>
#include <cuda_fp16.h>
#include <cstdint>

// Fixed shapes from reference setup_inputs
#define B_   16
#define C_   8
#define N_   262144                     // 512*512
#define THREADS 256
#define WARPS (THREADS / 32)            // 8
#define WPX 64                          // pixels per warp per stage-unit
#define DEPTH 3
#define NPART 73                        // 64 S + 8 n + 1 lse-sum
#define CTAS_PER_BATCH 32
#define NBLK (B_ * CTAS_PER_BATCH)      // 512 <= 592 resident (4/SM) -> ONE wave
#define NSTAGE 16                       // 512 units / 32 CTAs, exact balance

#define SLOT_BYTES 2304                 // 8 ch * 256B + 256B targets
#define RING_BYTES (DEPTH * SLOT_BYTES) // 6912 per warp
#define DYN_SMEM (WARPS * RING_BYTES)   // 55296 -> 4 CTAs/SM fit (221KB)

// Swizzle: 16B granule g of channel ch stored at g ^ H(ch).
#define HSW(ch) ((((ch) & 1) << 2) | ((ch) >> 1))
#define SWZ(ch, g) ((uint32_t)((((g) ^ HSW(ch)) & 15)))

__device__ float g_part[NBLK * NPART];
__device__ float g_jout[B_];
__device__ int   g_cnt_b[B_];
__device__ int   g_cnt_f;

static __device__ __forceinline__ float lg2(float x) {
  float r; asm("lg2.approx.f32 %0, %1;" : "=f"(r) : "f"(x)); return r;
}
static __device__ __forceinline__ uint32_t smem_u32(const void* p) {
  uint32_t a;
  asm("{ .reg .u64 t; cvta.to.shared.u64 t, %1; cvt.u32.u64 %0, t; }"
      : "=r"(a) : "l"(p));
  return a;
}
static __device__ __forceinline__ void cp_async16(uint32_t dst, const void* src) {
  asm volatile("cp.async.cg.shared.global [%0], [%1], 16;"
               :: "r"(dst), "l"(src) : "memory");
}
#define CP_COMMIT() asm volatile("cp.async.commit_group;" ::: "memory")
#define CP_WAIT(n)  asm volatile("cp.async.wait_group %0;" :: "n"(n) : "memory")

// pack two f32 -> f16x2; first source lands in HIGH half, second in LOW half.
static __device__ __forceinline__ uint32_t f16pack(float hi, float lo) {
  uint32_t r;
  asm("cvt.rn.f16x2.f32 %0, %1, %2;" : "=r"(r) : "f"(hi), "f"(lo));
  return r;
}
static __device__ __forceinline__ uint32_t mul_h2(uint32_t a, uint32_t b) {
  uint32_t r; asm("mul.rn.f16x2 %0, %1, %2;" : "=r"(r) : "r"(a), "r"(b));
  return r;
}
static __device__ __forceinline__ uint32_t ex2_h2(uint32_t a) {
  uint32_t r; asm("ex2.approx.f16x2 %0, %1;" : "=r"(r) : "r"(a));
  return r;
}
static __device__ __forceinline__ uint32_t add_h2(uint32_t a, uint32_t b) {
  uint32_t r; asm("add.rn.f16x2 %0, %1, %2;" : "=r"(r) : "r"(a), "r"(b));
  return r;
}

#define LOG2E 1.4426950408889634f
#define LN2   0.6931471805599453f
#define LOG2E_H2 0x3DC53DC5u            // f16x2 (log2e, log2e)

__global__ __launch_bounds__(THREADS, 4)
void jce_fused(const float* __restrict__ pred,
               const int* __restrict__ target,
               float* __restrict__ out) {
  extern __shared__ char dyn[];
  __shared__ bool amGroupLast, amFinal;
  const int bb = blockIdx.x;
  const int b  = bb >> 5;            // batch (CTAS_PER_BATCH = 32)
  const int j  = bb & 31;
  const int tid  = threadIdx.x;
  const int lane = tid & 31;
  const int wid  = tid >> 5;
  const int ci   = lane >> 2;        // MMA group id (m-row / n-col)
  const int tig  = lane & 3;         // thread-in-group

  // Warp's base pointers: batch + unit (j*NSTAGE stages) + warp sub-offset.
  const float* gp = pred + (size_t)b * C_ * N_ + j * (NSTAGE * 512) + wid * WPX;
  const int*   gt = target + (size_t)b * N_ + j * (NSTAGE * 512) + wid * WPX;
  const uint32_t ring_base = smem_u32(dyn) + wid * RING_BYTES;

  // Copy geometry: k-th cp.async handles ch = 2k + lh at 16B granule `of`.
  // Source collapses to ONE base + k*2*N immediate (register saver).
  const int lh = lane >> 4;          // 0/1
  const int of = lane & 15;
  const float* srcb = gp + (size_t)lh * N_ + of * 4;
  uint32_t cp_dst[4];
#pragma unroll
  for (int k = 0; k < 4; ++k) {
    const int ch = 2 * k + lh;
    cp_dst[k] = (uint32_t)(ch * 256) + SWZ(ch, of) * 16u;
  }

#define ISSUE_STAGE(st)                                                    \
  do {                                                                     \
    const uint32_t slot_ = ring_base + ((st) % DEPTH) * SLOT_BYTES;        \
    const float* s_ = srcb + (st) * 512;                                   \
    _Pragma("unroll")                                                      \
    for (int k = 0; k < 4; ++k)                                            \
      cp_async16(slot_ + cp_dst[k], s_ + (size_t)k * (2 * N_));            \
    if (lane < 16)                                                         \
      cp_async16(slot_ + (uint32_t)(C_ * 256 + lane * 16),                 \
                 gt + (st) * 512 + lane * 4);                              \
    CP_COMMIT();                                                           \
  } while (0)

  // Single merged D fragment: d0..d1 = S[ci][tig*2..+1]; d2..d3 = n.
  float d0 = 0, d1 = 0, d2 = 0, d3 = 0;
  float lsum2 = 0.0f;                  // LSE accumulated in log2 units
  const uint32_t ones2 = 0x3c003c00u;  // fp16 (1.0, 1.0)

  ISSUE_STAGE(0); ISSUE_STAGE(1);

#pragma unroll
  for (int st = 0; st < NSTAGE; ++st) {
    // Early refill: slot (st+2)%3 == (st-1)%3 was consumed last iteration.
    if (st + 2 < NSTAGE) { ISSUE_STAGE(st + 2); }
    else CP_COMMIT();   // keep group counting aligned for CP_WAIT

    CP_WAIT(2);         // 3 pending -> waits exactly until stage st lands
    const uint32_t slot = ring_base + (st % DEPTH) * SLOT_BYTES;

    // ---- LSE on this lane's own 2 pixels (px 2*lane, 2*lane+1),
    //      packed f16x2 exp path (2 tree accumulators) ----
    uint32_t sa = 0u, sb = 0u;
#pragma unroll
    for (int c = 0; c < 8; ++c) {
      float2 x;
      asm volatile("ld.shared.v2.f32 {%0, %1}, [%2];"
                   : "=f"(x.x), "=f"(x.y)
                   : "r"(slot + (uint32_t)(c * 256) +
                         SWZ(c, lane >> 1) * 16u + (uint32_t)((lane & 1) * 8)));
      const uint32_t e = ex2_h2(mul_h2(f16pack(x.y, x.x), LOG2E_H2));
      if (c & 1) sb = add_h2(sb, e); else sa = add_h2(sa, e);
    }
    const uint32_t sgm = add_h2(sa, sb);
    const float2 se = __half22float2(*reinterpret_cast<const __half2*>(&sgm));
    lsum2 += lg2(se.x) + lg2(se.y);

    // ---- 4 MMA K-chunks of 16 pixels each (k->pixel perm sigma:
    //      k=2t -> 4t, 2t+1 -> 4t+1, 2t+8 -> 4t+2, 2t+9 -> 4t+3) ----
#pragma unroll
    for (int q = 0; q < 4; ++q) {
      float4 a;
      asm volatile("ld.shared.v4.f32 {%0, %1, %2, %3}, [%4];"
                   : "=f"(a.x), "=f"(a.y), "=f"(a.z), "=f"(a.w)
                   : "r"(slot + (uint32_t)(ci * 256) +
                         SWZ(ci, q * 4 + tig) * 16u));
      const uint32_t ra0 = f16pack(a.y, a.x);   // k0,k1 (low = k0)
      const uint32_t ra2 = f16pack(a.w, a.z);   // k8,k9

      int4 v;
      asm volatile("ld.shared.v4.s32 {%0, %1, %2, %3}, [%4];"
                   : "=r"(v.x), "=r"(v.y), "=r"(v.z), "=r"(v.w)
                   : "r"(slot + 2048u + (uint32_t)(q * 64 + tig * 16)));
      const uint32_t rb0 = (v.x == ci ? 0x3c00u : 0u) |
                           (v.y == ci ? 0x3c000000u : 0u);
      const uint32_t rb1 = (v.z == ci ? 0x3c00u : 0u) |
                           (v.w == ci ? 0x3c000000u : 0u);

      asm volatile(
          "mma.sync.aligned.m16n8k16.row.col.f32.f16.f16.f32 "
          "{%0,%1,%2,%3}, {%4,%5,%6,%7}, {%8,%9}, {%0,%1,%2,%3};"
          : "+f"(d0), "+f"(d1), "+f"(d2), "+f"(d3)
          : "r"(ra0), "r"(ones2), "r"(ra2), "r"(ones2), "r"(rb0), "r"(rb1));
    }
  }
  CP_WAIT(0);

  float lsum = lsum2 * LN2;

  // warp-reduce lsum
  lsum += __shfl_xor_sync(0xFFFFFFFFu, lsum, 16);
  lsum += __shfl_xor_sync(0xFFFFFFFFu, lsum, 8);
  lsum += __shfl_xor_sync(0xFFFFFFFFu, lsum, 4);
  lsum += __shfl_xor_sync(0xFFFFFFFFu, lsum, 2);
  lsum += __shfl_xor_sync(0xFFFFFFFFu, lsum, 1);

  // Per-warp 73 partials into this warp's (now idle) ring area.
  float* wsc = reinterpret_cast<float*>(dyn + (size_t)wid * RING_BYTES);
  *reinterpret_cast<float2*>(wsc + ci * 8 + tig * 2) = make_float2(d0, d1);
  if (ci == 0)
    *reinterpret_cast<float2*>(wsc + 64 + tig * 2) = make_float2(d2, d3);
  if (lane == 0) wsc[72] = lsum;
  __syncthreads();

  if (tid < NPART) {
    float acc = 0.0f;
#pragma unroll
    for (int w2 = 0; w2 < WARPS; ++w2)
      acc += reinterpret_cast<const float*>(dyn + (size_t)w2 * RING_BYTES)[tid];
    g_part[bb * NPART + tid] = acc;
  }

  // ---- per-batch group-last reduction (16 run in parallel) ----
  __threadfence();
  if (tid == 0)
    amGroupLast = (atomicAdd(&g_cnt_b[b], 1) == CTAS_PER_BATCH - 1);
  __syncthreads();
  if (!amGroupLast) return;
  __threadfence();

  float* tot = reinterpret_cast<float*>(dyn);        // 73 floats
  float* red = reinterpret_cast<float*>(dyn) + 128;  // 256 floats
  if (tid < NPART) {
    float acc = 0.0f;
#pragma unroll
    for (int sl = 0; sl < CTAS_PER_BATCH; ++sl)
      acc += g_part[(b * CTAS_PER_BATCH + sl) * NPART + tid];
    tot[tid] = acc;
  }
  __syncthreads();

  const float invB  = 1.0f / (float)B_;
  const float invBN = 1.0f / ((float)B_ * (float)N_);
  float contrib = 0.0f;
  if (tid < 64) {
    const int cii = tid >> 3, ck = tid & 7;
    if (cii != ck) {
      const float diag = tot[cii * 8 + cii] / tot[64 + cii];
      const float mm   = tot[cii * 8 + ck] / tot[64 + ck];
      contrib = -(LN2 * lg2(0.5f + 0.5f * (diag - mm))) * invB;
    } else {
      contrib = -tot[cii * 8 + cii] * invBN;      // -trace part of CE
      if (tid == 0) contrib += tot[72] * invBN;   // +lse-sum part of CE
    }
  }
  red[tid] = contrib;
  __syncthreads();
#pragma unroll
  for (int off = THREADS / 2; off > 0; off >>= 1) {
    if (tid < off) red[tid] += red[tid + off];
    __syncthreads();
  }
  if (tid == 0) g_jout[b] = red[0];

  // ---- final: last of the 16 group-last blocks sums 16 floats ----
  __threadfence();
  if (tid == 0)
    amFinal = (atomicAdd(&g_cnt_f, 1) == B_ - 1);
  __syncthreads();
  if (!amFinal) return;
  __threadfence();

  if (tid == 0) {
    float acc = 0.0f;
#pragma unroll
    for (int i = 0; i < B_; ++i) acc += g_jout[i];
    out[0] = acc;
#pragma unroll
    for (int i = 0; i < B_; ++i) g_cnt_b[i] = 0;
    g_cnt_f = 0;
  }
}

extern "C" void kernel_launch(void* const* d_in, const int* in_sizes, int n_in,
                              void* d_out, int out_size) {
  const float* pred = (const float*)d_in[0];
  const int* target = (const int*)d_in[1];
  float* out = (float*)d_out;
  (void)in_sizes; (void)n_in; (void)out_size;

  cudaFuncSetAttribute(jce_fused, cudaFuncAttributeMaxDynamicSharedMemorySize,
                       DYN_SMEM);
  jce_fused<<<NBLK, THREADS, DYN_SMEM>>>(pred, target, out);
}

// round 17
// speedup vs baseline: 1.1016x; 1.1016x over previous
#include <cuda_runtime.h>
#include <cuda_fp16.h>
#include <cstdint>

// Fixed shapes from reference setup_inputs
#define B_   16
#define C_   8
#define N_   262144                     // 512*512
#define THREADS 256
#define WARPS (THREADS / 32)            // 8
#define WPX 64                          // pixels per warp per stage-unit
#define DEPTH 4
#define NPART 73                        // 64 S + 8 n + 1 lse-sum
#define CTAS_PER_BATCH 27
#define NBLK (B_ * CTAS_PER_BATCH)      // 432 <= 444 resident -> ONE wave
#define UNITS 512                       // stage-units per batch (512 px each)
#define UPC 19                          // units for CTAs 0..25; CTA 26 gets 18

#define SLOT_BYTES 2304                 // 8 ch * 256B + 256B targets
#define RING_BYTES (DEPTH * SLOT_BYTES) // 9216 per warp
#define DYN_SMEM (WARPS * RING_BYTES)   // 73728 -> 3 CTAs/SM (221KB, max ring)

// Swizzle: 16B granule g of channel ch stored at g ^ H(ch).
#define HSW(ch) ((((ch) & 1) << 2) | ((ch) >> 1))
#define SWZ(ch, g) ((uint32_t)((((g) ^ HSW(ch)) & 15)))

__device__ float g_part[NBLK * NPART];
__device__ float g_jout[B_];
__device__ int   g_cnt_b[B_];
__device__ int   g_cnt_f;

static __device__ __forceinline__ float lg2(float x) {
  float r; asm("lg2.approx.f32 %0, %1;" : "=f"(r) : "f"(x)); return r;
}
static __device__ __forceinline__ uint32_t smem_u32(const void* p) {
  uint32_t a;
  asm("{ .reg .u64 t; cvta.to.shared.u64 t, %1; cvt.u32.u64 %0, t; }"
      : "=r"(a) : "l"(p));
  return a;
}
static __device__ __forceinline__ void cp_async16(uint32_t dst, const void* src) {
  asm volatile("cp.async.cg.shared.global [%0], [%1], 16;"
               :: "r"(dst), "l"(src) : "memory");
}
#define CP_COMMIT() asm volatile("cp.async.commit_group;" ::: "memory")
#define CP_WAIT(n)  asm volatile("cp.async.wait_group %0;" :: "n"(n) : "memory")

// pack two f32 -> f16x2; first source lands in HIGH half, second in LOW half.
static __device__ __forceinline__ uint32_t f16pack(float hi, float lo) {
  uint32_t r;
  asm("cvt.rn.f16x2.f32 %0, %1, %2;" : "=r"(r) : "f"(hi), "f"(lo));
  return r;
}
static __device__ __forceinline__ uint32_t mul_h2(uint32_t a, uint32_t b) {
  uint32_t r; asm("mul.rn.f16x2 %0, %1, %2;" : "=r"(r) : "r"(a), "r"(b));
  return r;
}
static __device__ __forceinline__ uint32_t ex2_h2(uint32_t a) {
  uint32_t r; asm("ex2.approx.f16x2 %0, %1;" : "=r"(r) : "r"(a));
  return r;
}
static __device__ __forceinline__ uint32_t add_h2(uint32_t a, uint32_t b) {
  uint32_t r; asm("add.rn.f16x2 %0, %1, %2;" : "=r"(r) : "r"(a), "r"(b));
  return r;
}

#define LOG2E 1.4426950408889634f
#define LN2   0.6931471805599453f
#define LOG2E_H2 0x3DC53DC5u            // f16x2 (log2e, log2e)

__global__ __launch_bounds__(THREADS, 3)
void jce_fused(const float* __restrict__ pred,
               const int* __restrict__ target,
               float* __restrict__ out) {
  extern __shared__ char dyn[];
  __shared__ bool amGroupLast, amFinal;
  const int bb = blockIdx.x;
  const int b  = bb / CTAS_PER_BATCH;
  const int j  = bb % CTAS_PER_BATCH;
  const int nst = (j < CTAS_PER_BATCH - 1) ? UPC : (UNITS - UPC * (CTAS_PER_BATCH - 1));
  const int tid  = threadIdx.x;
  const int lane = tid & 31;
  const int wid  = tid >> 5;
  const int ci   = lane >> 2;        // MMA group id (m-row / n-col)
  const int tig  = lane & 3;         // thread-in-group

  // Warp's base pointers: batch + unit offset + warp sub-offset.
  const float* gp = pred + (size_t)b * C_ * N_ + j * (UPC * 512) + wid * WPX;
  const int*   gt = target + (size_t)b * N_ + j * (UPC * 512) + wid * WPX;
  const uint32_t ring_base = smem_u32(dyn) + wid * RING_BYTES;

  // Copy geometry (register-lean): k-th cp.async handles ch = 2k + lh at
  // granule `of`; source collapses to ONE base + k*2*N immediate.
  const int lh = lane >> 4;          // 0/1
  const int of = lane & 15;
  const float* srcb = gp + (size_t)lh * N_ + of * 4;
  uint32_t cp_dst[4];
#pragma unroll
  for (int k = 0; k < 4; ++k) {
    const int ch = 2 * k + lh;
    cp_dst[k] = (uint32_t)(ch * 256) + SWZ(ch, of) * 16u;
  }

#define ISSUE_STAGE(st)                                                    \
  do {                                                                     \
    const uint32_t slot_ = ring_base + ((st) & (DEPTH - 1)) * SLOT_BYTES;  \
    const float* s_ = srcb + (st) * 512;                                   \
    _Pragma("unroll")                                                      \
    for (int k = 0; k < 4; ++k)                                            \
      cp_async16(slot_ + cp_dst[k], s_ + (size_t)k * (2 * N_));            \
    if (lane < 16)                                                         \
      cp_async16(slot_ + (uint32_t)(C_ * 256 + lane * 16),                 \
                 gt + (st) * 512 + lane * 4);                              \
    CP_COMMIT();                                                           \
  } while (0)

  // D fragments: dX[0..1] = S[ci][tig*2 .. +1]; dX[2..3] = n[tig*2 .. +1]
  float dA0 = 0, dA1 = 0, dA2 = 0, dA3 = 0;   // even K-chunks
  float dB0 = 0, dB1 = 0, dB2 = 0, dB3 = 0;   // odd K-chunks
  float lsum2 = 0.0f;                  // LSE accumulated in log2 units
  const uint32_t ones2 = 0x3c003c00u;  // fp16 (1.0, 1.0)

  ISSUE_STAGE(0); ISSUE_STAGE(1); ISSUE_STAGE(2);

#pragma unroll 2
  for (int st = 0; st < nst; ++st) {
    // Early refill: slot (st+3)&3 == (st-1)&3 was consumed last iteration.
    if (st + 3 < nst) { ISSUE_STAGE(st + 3); }
    else CP_COMMIT();   // keep group counting aligned for CP_WAIT

    CP_WAIT(3);         // 4 pending -> waits exactly until stage st lands
    const uint32_t slot = ring_base + (st & (DEPTH - 1)) * SLOT_BYTES;

    // ---- LSE on this lane's own 2 pixels (px 2*lane, 2*lane+1),
    //      packed f16x2 exp path (2 tree accumulators) ----
    uint32_t sa = 0u, sb = 0u;
#pragma unroll
    for (int c = 0; c < 8; ++c) {
      float2 x;
      asm volatile("ld.shared.v2.f32 {%0, %1}, [%2];"
                   : "=f"(x.x), "=f"(x.y)
                   : "r"(slot + (uint32_t)(c * 256) +
                         SWZ(c, lane >> 1) * 16u + (uint32_t)((lane & 1) * 8)));
      const uint32_t e = ex2_h2(mul_h2(f16pack(x.y, x.x), LOG2E_H2));
      if (c & 1) sb = add_h2(sb, e); else sa = add_h2(sa, e);
    }
    const uint32_t sgm = add_h2(sa, sb);
    const float2 se = __half22float2(*reinterpret_cast<const __half2*>(&sgm));
    lsum2 += lg2(se.x) + lg2(se.y);

    // ---- 4 MMA K-chunks of 16 pixels each (k->pixel perm sigma:
    //      k=2t -> 4t, 2t+1 -> 4t+1, 2t+8 -> 4t+2, 2t+9 -> 4t+3) ----
#pragma unroll
    for (int q = 0; q < 4; ++q) {
      float4 a;
      asm volatile("ld.shared.v4.f32 {%0, %1, %2, %3}, [%4];"
                   : "=f"(a.x), "=f"(a.y), "=f"(a.z), "=f"(a.w)
                   : "r"(slot + (uint32_t)(ci * 256) +
                         SWZ(ci, q * 4 + tig) * 16u));
      const uint32_t ra0 = f16pack(a.y, a.x);   // k0,k1 (low = k0)
      const uint32_t ra2 = f16pack(a.w, a.z);   // k8,k9

      int4 v;
      asm volatile("ld.shared.v4.s32 {%0, %1, %2, %3}, [%4];"
                   : "=r"(v.x), "=r"(v.y), "=r"(v.z), "=r"(v.w)
                   : "r"(slot + 2048u + (uint32_t)(q * 64 + tig * 16)));
      const uint32_t rb0 = (v.x == ci ? 0x3c00u : 0u) |
                           (v.y == ci ? 0x3c000000u : 0u);
      const uint32_t rb1 = (v.z == ci ? 0x3c00u : 0u) |
                           (v.w == ci ? 0x3c000000u : 0u);

      if (q & 1)
        asm volatile(
            "mma.sync.aligned.m16n8k16.row.col.f32.f16.f16.f32 "
            "{%0,%1,%2,%3}, {%4,%5,%6,%7}, {%8,%9}, {%0,%1,%2,%3};"
            : "+f"(dB0), "+f"(dB1), "+f"(dB2), "+f"(dB3)
            : "r"(ra0), "r"(ones2), "r"(ra2), "r"(ones2), "r"(rb0), "r"(rb1));
      else
        asm volatile(
            "mma.sync.aligned.m16n8k16.row.col.f32.f16.f16.f32 "
            "{%0,%1,%2,%3}, {%4,%5,%6,%7}, {%8,%9}, {%0,%1,%2,%3};"
            : "+f"(dA0), "+f"(dA1), "+f"(dA2), "+f"(dA3)
            : "r"(ra0), "r"(ones2), "r"(ra2), "r"(ones2), "r"(rb0), "r"(rb1));
    }
  }
  CP_WAIT(0);

  const float d0 = dA0 + dB0, d1 = dA1 + dB1;
  const float d2 = dA2 + dB2, d3 = dA3 + dB3;
  float lsum = lsum2 * LN2;

  // warp-reduce lsum
  lsum += __shfl_xor_sync(0xFFFFFFFFu, lsum, 16);
  lsum += __shfl_xor_sync(0xFFFFFFFFu, lsum, 8);
  lsum += __shfl_xor_sync(0xFFFFFFFFu, lsum, 4);
  lsum += __shfl_xor_sync(0xFFFFFFFFu, lsum, 2);
  lsum += __shfl_xor_sync(0xFFFFFFFFu, lsum, 1);

  // Per-warp 73 partials into this warp's (now idle) ring area.
  float* wsc = reinterpret_cast<float*>(dyn + (size_t)wid * RING_BYTES);
  *reinterpret_cast<float2*>(wsc + ci * 8 + tig * 2) = make_float2(d0, d1);
  if (ci == 0)
    *reinterpret_cast<float2*>(wsc + 64 + tig * 2) = make_float2(d2, d3);
  if (lane == 0) wsc[72] = lsum;
  __syncthreads();

  if (tid < NPART) {
    float acc = 0.0f;
#pragma unroll
    for (int w2 = 0; w2 < WARPS; ++w2)
      acc += reinterpret_cast<const float*>(dyn + (size_t)w2 * RING_BYTES)[tid];
    g_part[bb * NPART + tid] = acc;
  }

  // ---- per-batch group-last reduction (16 run in parallel) ----
  __threadfence();
  if (tid == 0)
    amGroupLast = (atomicAdd(&g_cnt_b[b], 1) == CTAS_PER_BATCH - 1);
  __syncthreads();
  if (!amGroupLast) return;
  __threadfence();

  float* tot = reinterpret_cast<float*>(dyn);        // 73 floats
  float* red = reinterpret_cast<float*>(dyn) + 128;  // 256 floats
  if (tid < NPART) {
    float acc = 0.0f;
#pragma unroll
    for (int sl = 0; sl < CTAS_PER_BATCH; ++sl)
      acc += g_part[(b * CTAS_PER_BATCH + sl) * NPART + tid];
    tot[tid] = acc;
  }
  __syncthreads();

  const float invB  = 1.0f / (float)B_;
  const float invBN = 1.0f / ((float)B_ * (float)N_);
  float contrib = 0.0f;
  if (tid < 64) {
    const int cii = tid >> 3, ck = tid & 7;
    if (cii != ck) {
      const float diag = tot[cii * 8 + cii] / tot[64 + cii];
      const float mm   = tot[cii * 8 + ck] / tot[64 + ck];
      contrib = -(LN2 * lg2(0.5f + 0.5f * (diag - mm))) * invB;
    } else {
      contrib = -tot[cii * 8 + cii] * invBN;      // -trace part of CE
      if (tid == 0) contrib += tot[72] * invBN;   // +lse-sum part of CE
    }
  }
  red[tid] = contrib;
  __syncthreads();
#pragma unroll
  for (int off = THREADS / 2; off > 0; off >>= 1) {
    if (tid < off) red[tid] += red[tid + off];
    __syncthreads();
  }
  if (tid == 0) g_jout[b] = red[0];

  // ---- final: last of the 16 group-last blocks sums 16 floats ----
  __threadfence();
  if (tid == 0)
    amFinal = (atomicAdd(&g_cnt_f, 1) == B_ - 1);
  __syncthreads();
  if (!amFinal) return;
  __threadfence();

  if (tid == 0) {
    float acc = 0.0f;
#pragma unroll
    for (int i = 0; i < B_; ++i) acc += g_jout[i];
    out[0] = acc;
#pragma unroll
    for (int i = 0; i < B_; ++i) g_cnt_b[i] = 0;
    g_cnt_f = 0;
  }
}

extern "C" void kernel_launch(void* const* d_in, const int* in_sizes, int n_in,
                              void* d_out, int out_size) {
  const float* pred = (const float*)d_in[0];
  const int* target = (const int*)d_in[1];
  float* out = (float*)d_out;
  (void)in_sizes; (void)n_in; (void)out_size;

  cudaFuncSetAttribute(jce_fused, cudaFuncAttributeMaxDynamicSharedMemorySize,
                       DYN_SMEM);
  jce_fused<<<NBLK, THREADS, DYN_SMEM>>>(pred, target, out);
}